// round 12
// baseline (speedup 1.0000x reference)
#include <cuda_runtime.h>
#include <cuda_bf16.h>
#include <stdint.h>

// ---------------------------------------------------------------------------
// SPMoEAdaptor fused (2 soft-MoE layers + residual), sm_103a. R12:
// n-split with 16 f-cols per warp (B in regs, Bx[4][2][2]) and m-split across
// warp groups: CTA=256 threads / 256 tokens; warp w covers m-group (w>>2)
// [128 tokens] x f-slice ((w&3)*16). Halves A-fragment LDS traffic vs R9.
// ---------------------------------------------------------------------------

#define DD 64
#define NW 264           // 256 expert cols + 4 gate cols + 4 zero pad
#define RS 72            // bf16 row stride in token buffers (144B, LDSM conflict-free)

// Prepacked weights: [layer][n][j][kk]; uint2 = {bf16x2(d=kk*16+2j,+1), bf16x2(d+8,+9)}
__device__ __align__(16) uint2 g_wpack[2][NW][4][4];
__device__ float g_c[2][4][DD];   // c_e[f] = sum_d b[e,d]*W[e,d,f]

__device__ __forceinline__ uint32_t pack_bf16x2(float lo, float hi) {
    uint32_t r; asm("cvt.rn.bf16x2.f32 %0, %1, %2;" : "=r"(r) : "f"(hi), "f"(lo)); return r;
}
__device__ __forceinline__ float bf_lo(uint32_t u) { return __uint_as_float(u << 16); }
__device__ __forceinline__ float bf_hi(uint32_t u) { return __uint_as_float(u & 0xffff0000u); }

__device__ __forceinline__ uint32_t smem_u32(const void* p) {
    uint32_t a; asm("{ .reg .u64 t; cvta.to.shared.u64 t, %1; cvt.u32.u64 %0, t; }" : "=r"(a) : "l"(p)); return a;
}
__device__ __forceinline__ void sts32(uint32_t a, uint32_t v) {
    asm volatile("st.shared.b32 [%0], %1;" :: "r"(a), "r"(v) : "memory");
}
__device__ __forceinline__ void sts64(uint32_t a, uint32_t v0, uint32_t v1) {
    asm volatile("st.shared.v2.b32 [%0], {%1,%2};" :: "r"(a), "r"(v0), "r"(v1) : "memory");
}
__device__ __forceinline__ uint2 lds64(uint32_t a) {
    uint2 v; asm volatile("ld.shared.v2.b32 {%0,%1}, [%2];" : "=r"(v.x), "=r"(v.y) : "r"(a)); return v;
}
__device__ __forceinline__ float4 ldsf4(uint32_t a) {
    float4 v; asm volatile("ld.shared.v4.f32 {%0,%1,%2,%3}, [%4];"
        : "=f"(v.x), "=f"(v.y), "=f"(v.z), "=f"(v.w) : "r"(a)); return v;
}
__device__ __forceinline__ void stsf4(uint32_t a, float4 v) {
    asm volatile("st.shared.v4.f32 [%0], {%1,%2,%3,%4};" :: "r"(a), "f"(v.x), "f"(v.y), "f"(v.z), "f"(v.w) : "memory");
}
__device__ __forceinline__ float2 ldsf2(uint32_t a) {
    float2 v; asm volatile("ld.shared.v2.f32 {%0,%1}, [%2];" : "=f"(v.x), "=f"(v.y) : "r"(a)); return v;
}
__device__ __forceinline__ void ldsm_x4(uint32_t r[4], uint32_t a) {
    asm volatile("ldmatrix.sync.aligned.m8n8.x4.shared.b16 {%0,%1,%2,%3}, [%4];"
        : "=r"(r[0]), "=r"(r[1]), "=r"(r[2]), "=r"(r[3]) : "r"(a));
}
__device__ __forceinline__ void mma16816(float c[4], const uint32_t a[4], uint32_t b0, uint32_t b1) {
    asm volatile(
        "mma.sync.aligned.m16n8k16.row.col.f32.bf16.bf16.f32 "
        "{%0,%1,%2,%3}, {%4,%5,%6,%7}, {%8,%9}, {%0,%1,%2,%3};"
        : "+f"(c[0]), "+f"(c[1]), "+f"(c[2]), "+f"(c[3])
        : "r"(a[0]), "r"(a[1]), "r"(a[2]), "r"(a[3]), "r"(b0), "r"(b1));
}

// ------------------------------ prep kernel --------------------------------
__global__ void prep_kernel(const float* __restrict__ wg_a, const float* __restrict__ we_a,
                            const float* __restrict__ be_a,
                            const float* __restrict__ wg_b, const float* __restrict__ we_b,
                            const float* __restrict__ be_b) {
    const int L = blockIdx.x;
    const float* wg = L ? wg_b : wg_a;
    const float* we = L ? we_b : we_a;
    const float* be = L ? be_b : be_a;

    for (int idx = threadIdx.x; idx < NW * 16; idx += blockDim.x) {
        int n  = idx >> 4;
        int j  = (idx >> 2) & 3;
        int kk = idx & 3;
        float v[4];
#pragma unroll
        for (int h = 0; h < 4; h++) {
            int d = kk * 16 + 2 * j + (h >> 1) * 8 + (h & 1);
            float w;
            if (n < 256)        w = we[((n >> 6) * DD + d) * DD + (n & 63)]; // W_e[d][f]
            else if (n < 260)   w = wg[d * 4 + (n - 256)];                   // w_gate[d][e]
            else                w = 0.0f;
            v[h] = w;
        }
        uint2 u;
        u.x = pack_bf16x2(v[0], v[1]);
        u.y = pack_bf16x2(v[2], v[3]);
        g_wpack[L][n][j][kk] = u;
    }
    for (int idx = threadIdx.x; idx < 4 * DD; idx += blockDim.x) {
        int e = idx >> 6, f = idx & 63;
        float s = 0.0f;
        for (int d = 0; d < DD; d++) s += be[e * DD + d] * we[(e * DD + d) * DD + f];
        g_c[L][e][f] = s;
    }
}

// ------------------------------ main kernel --------------------------------
__global__ __launch_bounds__(256, 2)
void moe_main_kernel(const float* __restrict__ x, float* __restrict__ out, int Ntok) {
    extern __shared__ __align__(16) uint8_t smraw[];
    const uint32_t base = smem_u32(smraw);
    const uint32_t BUFA = base;                  // [256][RS] bf16 (x / h2)
    const uint32_t BUFB = base + 256 * RS * 2;   // [256][RS] bf16 (h1)
    const uint32_t GSM  = BUFB + 256 * RS * 2;   // [256][4] f32 gates
    const uint32_t CSM  = GSM + 256 * 16;        // [2][4][64] f32 bias

    const int tid  = threadIdx.x;
    const int w    = tid >> 5;
    const int lane = tid & 31;
    const int qr   = lane >> 2;
    const int qc   = lane & 3;
    const int mg   = w >> 2;                     // m-group: tokens mg*128..+127
    const int fq   = w & 3;                      // f-slice base = fq*16
    const long tok0 = (long)blockIdx.x * 256;

    for (int i = tid; i < 512; i += 256)
        sts32(CSM + i * 4, ((const uint32_t*)g_c)[i]);

    // ---- stage x -> BUFA (bf16), fully coalesced ----
#pragma unroll
    for (int i = 0; i < 16; i++) {
        int idx = i * 1024 + tid * 4;            // 0..16383 floats
        int row = idx >> 6, col = idx & 63;
        long r = tok0 + row;
        float4 v = (r < Ntok) ? *(const float4*)(x + r * 64 + col)
                              : make_float4(0.f, 0.f, 0.f, 0.f);
        sts64(BUFA + (row * RS + col) * 2, pack_bf16x2(v.x, v.y), pack_bf16x2(v.z, v.w));
    }
    __syncthreads();

    const uint32_t lrow = (uint32_t)(lane & 15) * (RS * 2) + (uint32_t)(lane >> 4) * 16;
    const uint4* gw4 = (const uint4*)g_wpack;    // 8 uint4 per n-row

#pragma unroll
    for (int L = 0; L < 2; L++) {
        const uint32_t inb  = (L == 0) ? BUFA : BUFB;
        const uint32_t outb = (L == 0) ? BUFB : BUFA;
        const uint32_t wbase = (uint32_t)L * NW * 8;

        // ---- expert B-slices into registers: n = e*64 + fq*16 + nt*8 + qr ----
        uint4 Bx[4][2][2];
#pragma unroll
        for (int e = 0; e < 4; e++)
#pragma unroll
            for (int nt = 0; nt < 2; nt++) {
                const uint4* p = gw4 + wbase + (uint32_t)(e * 64 + fq * 16 + nt * 8 + qr) * 8 + qc * 2;
                Bx[e][nt][0] = p[0];
                Bx[e][nt][1] = p[1];
            }

        // ---- gate phase: warp w handles m-tiles {2w, 2w+1} ----
#pragma unroll
        for (int g = 0; g < 2; g++) {
            const uint4* pg = gw4 + wbase + (uint32_t)(256 + qr) * 8 + qc * 2;
            uint4 Bg0 = pg[0], Bg1 = pg[1];
            uint32_t Af[4][4];
            uint32_t ab = inb + (uint32_t)(w * 32 + g * 16) * (RS * 2) + lrow;
#pragma unroll
            for (int c = 0; c < 4; c++) ldsm_x4(Af[c], ab + c * 32);
            float acc[4] = {0.f, 0.f, 0.f, 0.f};
            mma16816(acc, Af[0], Bg0.x, Bg0.y);
            mma16816(acc, Af[1], Bg0.z, Bg0.w);
            mma16816(acc, Af[2], Bg1.x, Bg1.y);
            mma16816(acc, Af[3], Bg1.z, Bg1.w);
            const unsigned full = 0xffffffffu;
            const int qb = lane & ~3;
            float l0 = __shfl_sync(full, acc[0], qb);
            float l1 = __shfl_sync(full, acc[1], qb);
            float l2 = __shfl_sync(full, acc[0], qb + 1);
            float l3 = __shfl_sync(full, acc[1], qb + 1);
            float m0 = __shfl_sync(full, acc[2], qb);
            float m1 = __shfl_sync(full, acc[3], qb);
            float m2 = __shfl_sync(full, acc[2], qb + 1);
            float m3 = __shfl_sync(full, acc[3], qb + 1);
            float mxl = fmaxf(fmaxf(l0, l1), fmaxf(l2, l3));
            float e0 = __expf(l0 - mxl), e1 = __expf(l1 - mxl), e2 = __expf(l2 - mxl), e3 = __expf(l3 - mxl);
            float inv = 1.0f / (e0 + e1 + e2 + e3);
            float4 glo = make_float4(e0 * inv, e1 * inv, e2 * inv, e3 * inv);
            float mxh = fmaxf(fmaxf(m0, m1), fmaxf(m2, m3));
            float f0 = __expf(m0 - mxh), f1 = __expf(m1 - mxh), f2 = __expf(m2 - mxh), f3 = __expf(m3 - mxh);
            float inh = 1.0f / (f0 + f1 + f2 + f3);
            float4 ghi = make_float4(f0 * inh, f1 * inh, f2 * inh, f3 * inh);
            if (qc == 0) {
                stsf4(GSM + (uint32_t)(w * 32 + g * 16 + qr) * 16, glo);
                stsf4(GSM + (uint32_t)(w * 32 + g * 16 + qr + 8) * 16, ghi);
            }
        }
        __syncthreads();

        // ---- main: 8 m-tiles of this warp's m-group through its 16-col f-slice ----
#pragma unroll
        for (int mt = 0; mt < 8; mt++) {
            const int row0 = mg * 128 + mt * 16;
            uint32_t Af[4][4];
            uint32_t ab = inb + (uint32_t)row0 * (RS * 2) + lrow;
#pragma unroll
            for (int c = 0; c < 4; c++) ldsm_x4(Af[c], ab + c * 32);
            float4 gl = ldsf4(GSM + (uint32_t)(row0 + qr) * 16);
            float4 gh = ldsf4(GSM + (uint32_t)(row0 + qr + 8) * 16);
            const float gle[4] = {gl.x, gl.y, gl.z, gl.w};
            const float ghe[4] = {gh.x, gh.y, gh.z, gh.w};
            float h[2][4] = {{0.f, 0.f, 0.f, 0.f}, {0.f, 0.f, 0.f, 0.f}};
#pragma unroll
            for (int e = 0; e < 4; e++) {
#pragma unroll
                for (int nt = 0; nt < 2; nt++) {
                    float Y[4] = {0.f, 0.f, 0.f, 0.f};
                    mma16816(Y, Af[0], Bx[e][nt][0].x, Bx[e][nt][0].y);
                    mma16816(Y, Af[1], Bx[e][nt][0].z, Bx[e][nt][0].w);
                    mma16816(Y, Af[2], Bx[e][nt][1].x, Bx[e][nt][1].y);
                    mma16816(Y, Af[3], Bx[e][nt][1].z, Bx[e][nt][1].w);
                    h[nt][0] = fmaf(gle[e], Y[0], h[nt][0]);
                    h[nt][1] = fmaf(gle[e], Y[1], h[nt][1]);
                    h[nt][2] = fmaf(ghe[e], Y[2], h[nt][2]);
                    h[nt][3] = fmaf(ghe[e], Y[3], h[nt][3]);
                }
            }
            // bias correction from smem (saves regs; tiny LDS)
#pragma unroll
            for (int e = 0; e < 4; e++) {
                float2 c0 = ldsf2(CSM + ((uint32_t)L * 256 + e * 64 + fq * 16 + 2 * qc) * 4);
                float2 c1 = ldsf2(CSM + ((uint32_t)L * 256 + e * 64 + fq * 16 + 8 + 2 * qc) * 4);
                h[0][0] = fmaf(-gle[e], c0.x, h[0][0]);
                h[0][1] = fmaf(-gle[e], c0.y, h[0][1]);
                h[0][2] = fmaf(-ghe[e], c0.x, h[0][2]);
                h[0][3] = fmaf(-ghe[e], c0.y, h[0][3]);
                h[1][0] = fmaf(-gle[e], c1.x, h[1][0]);
                h[1][1] = fmaf(-gle[e], c1.y, h[1][1]);
                h[1][2] = fmaf(-ghe[e], c1.x, h[1][2]);
                h[1][3] = fmaf(-ghe[e], c1.y, h[1][3]);
            }
#pragma unroll
            for (int nt = 0; nt < 2; nt++) {
                uint32_t oc = (uint32_t)(fq * 16 + nt * 8 + 2 * qc) * 2;
                sts32(outb + (uint32_t)(row0 + qr) * (RS * 2) + oc, pack_bf16x2(h[nt][0], h[nt][1]));
                sts32(outb + (uint32_t)(row0 + qr + 8) * (RS * 2) + oc, pack_bf16x2(h[nt][2], h[nt][3]));
            }
        }
        __syncthreads();
    }

    // ---- epilogue: h2 (BUFA) + residual x (fp32, L2-hot) -> out, coalesced ----
#pragma unroll
    for (int i = 0; i < 16; i++) {
        int idx = i * 1024 + tid * 4;
        int row = idx >> 6, col = idx & 63;
        long r = tok0 + row;
        if (r < Ntok) {
            uint2 hp = lds64(BUFA + (row * RS + col) * 2);
            float4 xr = *(const float4*)(x + r * 64 + col);
            float4 o = make_float4(bf_lo(hp.x) + xr.x, bf_hi(hp.x) + xr.y,
                                   bf_lo(hp.y) + xr.z, bf_hi(hp.y) + xr.w);
            *(float4*)(out + r * 64 + col) = o;
        }
    }
}

// ------------------------------ launch -------------------------------------
extern "C" void kernel_launch(void* const* d_in, const int* in_sizes, int n_in,
                              void* d_out, int out_size) {
    const float* x    = (const float*)d_in[0];
    const float* wg_a = (const float*)d_in[1];
    const float* we_a = (const float*)d_in[2];
    const float* be_a = (const float*)d_in[3];
    const float* wg_b = (const float*)d_in[4];
    const float* we_b = (const float*)d_in[5];
    const float* be_b = (const float*)d_in[6];
    const int Ntok = in_sizes[0] / DD;

    prep_kernel<<<2, 256>>>(wg_a, we_a, be_a, wg_b, we_b, be_b);

    const int smem_bytes = 2 * 256 * RS * 2 + 256 * 16 + 512 * 4;  // 79872
    cudaFuncSetAttribute(moe_main_kernel, cudaFuncAttributeMaxDynamicSharedMemorySize, smem_bytes);

    const int grid = (Ntok + 255) / 256;
    moe_main_kernel<<<grid, 256, smem_bytes>>>(x, (float*)d_out, Ntok);
}

// round 13
// speedup vs baseline: 1.0905x; 1.0905x over previous
#include <cuda_runtime.h>
#include <cuda_bf16.h>
#include <stdint.h>

// ---------------------------------------------------------------------------
// SPMoEAdaptor fused (2 soft-MoE layers + residual), sm_103a. R13 = R9 base
// (n-split, 8 f-cols/warp in regs, 128 tokens/CTA) + software-pipelined
// A-fragment loads (double-buffered ldmatrix) to hide LDSM/LDS latency under
// MMA issue. Pure scheduling change vs R9 (146.2us best).
// ---------------------------------------------------------------------------

#define DD 64
#define NW 264           // 256 expert cols + 4 gate cols + 4 zero pad
#define RS 72            // bf16 row stride in token buffers (144B, LDSM conflict-free)

__device__ __align__(16) uint2 g_wpack[2][NW][4][4];
__device__ float g_c[2][4][DD];   // c_e[f] = sum_d b[e,d]*W[e,d,f]

__device__ __forceinline__ uint32_t pack_bf16x2(float lo, float hi) {
    uint32_t r; asm("cvt.rn.bf16x2.f32 %0, %1, %2;" : "=r"(r) : "f"(hi), "f"(lo)); return r;
}
__device__ __forceinline__ float bf_lo(uint32_t u) { return __uint_as_float(u << 16); }
__device__ __forceinline__ float bf_hi(uint32_t u) { return __uint_as_float(u & 0xffff0000u); }

__device__ __forceinline__ uint32_t smem_u32(const void* p) {
    uint32_t a; asm("{ .reg .u64 t; cvta.to.shared.u64 t, %1; cvt.u32.u64 %0, t; }" : "=r"(a) : "l"(p)); return a;
}
__device__ __forceinline__ void sts32(uint32_t a, uint32_t v) {
    asm volatile("st.shared.b32 [%0], %1;" :: "r"(a), "r"(v) : "memory");
}
__device__ __forceinline__ void sts64(uint32_t a, uint32_t v0, uint32_t v1) {
    asm volatile("st.shared.v2.b32 [%0], {%1,%2};" :: "r"(a), "r"(v0), "r"(v1) : "memory");
}
__device__ __forceinline__ uint2 lds64(uint32_t a) {
    uint2 v; asm volatile("ld.shared.v2.b32 {%0,%1}, [%2];" : "=r"(v.x), "=r"(v.y) : "r"(a)); return v;
}
__device__ __forceinline__ float4 ldsf4(uint32_t a) {
    float4 v; asm volatile("ld.shared.v4.f32 {%0,%1,%2,%3}, [%4];"
        : "=f"(v.x), "=f"(v.y), "=f"(v.z), "=f"(v.w) : "r"(a)); return v;
}
__device__ __forceinline__ void stsf4(uint32_t a, float4 v) {
    asm volatile("st.shared.v4.f32 [%0], {%1,%2,%3,%4};" :: "r"(a), "f"(v.x), "f"(v.y), "f"(v.z), "f"(v.w) : "memory");
}
__device__ __forceinline__ float2 ldsf2(uint32_t a) {
    float2 v; asm volatile("ld.shared.v2.f32 {%0,%1}, [%2];" : "=f"(v.x), "=f"(v.y) : "r"(a)); return v;
}
__device__ __forceinline__ void ldsm_x4(uint32_t r[4], uint32_t a) {
    asm volatile("ldmatrix.sync.aligned.m8n8.x4.shared.b16 {%0,%1,%2,%3}, [%4];"
        : "=r"(r[0]), "=r"(r[1]), "=r"(r[2]), "=r"(r[3]) : "r"(a));
}
__device__ __forceinline__ void mma16816(float c[4], const uint32_t a[4], uint32_t b0, uint32_t b1) {
    asm volatile(
        "mma.sync.aligned.m16n8k16.row.col.f32.bf16.bf16.f32 "
        "{%0,%1,%2,%3}, {%4,%5,%6,%7}, {%8,%9}, {%0,%1,%2,%3};"
        : "+f"(c[0]), "+f"(c[1]), "+f"(c[2]), "+f"(c[3])
        : "r"(a[0]), "r"(a[1]), "r"(a[2]), "r"(a[3]), "r"(b0), "r"(b1));
}

// ------------------------------ prep kernel --------------------------------
__global__ void prep_kernel(const float* __restrict__ wg_a, const float* __restrict__ we_a,
                            const float* __restrict__ be_a,
                            const float* __restrict__ wg_b, const float* __restrict__ we_b,
                            const float* __restrict__ be_b) {
    const int L = blockIdx.x;
    const float* wg = L ? wg_b : wg_a;
    const float* we = L ? we_b : we_a;
    const float* be = L ? be_b : be_a;

    for (int idx = threadIdx.x; idx < NW * 16; idx += blockDim.x) {
        int n  = idx >> 4;
        int j  = (idx >> 2) & 3;
        int kk = idx & 3;
        float v[4];
#pragma unroll
        for (int h = 0; h < 4; h++) {
            int d = kk * 16 + 2 * j + (h >> 1) * 8 + (h & 1);
            float w;
            if (n < 256)        w = we[((n >> 6) * DD + d) * DD + (n & 63)]; // W_e[d][f]
            else if (n < 260)   w = wg[d * 4 + (n - 256)];                   // w_gate[d][e]
            else                w = 0.0f;
            v[h] = w;
        }
        uint2 u;
        u.x = pack_bf16x2(v[0], v[1]);
        u.y = pack_bf16x2(v[2], v[3]);
        g_wpack[L][n][j][kk] = u;
    }
    for (int idx = threadIdx.x; idx < 4 * DD; idx += blockDim.x) {
        int e = idx >> 6, f = idx & 63;
        float s = 0.0f;
        for (int d = 0; d < DD; d++) s += be[e * DD + d] * we[(e * DD + d) * DD + f];
        g_c[L][e][f] = s;
    }
}

// ------------------------------ main kernel --------------------------------
__global__ __launch_bounds__(256, 2)
void moe_main_kernel(const float* __restrict__ x, float* __restrict__ out, int Ntok) {
    extern __shared__ __align__(16) uint8_t smraw[];
    const uint32_t base = smem_u32(smraw);
    const uint32_t BUFA = base;                  // [128][RS] bf16 (x / h2)
    const uint32_t BUFB = base + 128 * RS * 2;   // [128][RS] bf16 (h1)
    const uint32_t GSM  = BUFB + 128 * RS * 2;   // [128][4] f32 gates
    const uint32_t CSM  = GSM + 128 * 16;        // [2][4][64] f32 bias

    const int tid  = threadIdx.x;
    const int w    = tid >> 5;
    const int lane = tid & 31;
    const int qr   = lane >> 2;
    const int qc   = lane & 3;
    const long tok0 = (long)blockIdx.x * 128;

    for (int i = tid; i < 512; i += 256)
        sts32(CSM + i * 4, ((const uint32_t*)g_c)[i]);

    // ---- stage x -> BUFA (bf16), fully coalesced ----
#pragma unroll
    for (int i = 0; i < 8; i++) {
        int idx = w * 1024 + i * 128 + lane * 4;     // 0..8191 floats
        int row = idx >> 6, col = idx & 63;
        long r = tok0 + row;
        float4 v = (r < Ntok) ? *(const float4*)(x + r * 64 + col)
                              : make_float4(0.f, 0.f, 0.f, 0.f);
        sts64(BUFA + (row * RS + col) * 2, pack_bf16x2(v.x, v.y), pack_bf16x2(v.z, v.w));
    }
    __syncthreads();

    const uint32_t lrow = (uint32_t)(lane & 15) * (RS * 2) + (uint32_t)(lane >> 4) * 16;
    const uint4* gw4 = (const uint4*)g_wpack;    // 8 uint4 per n-row

#pragma unroll
    for (int L = 0; L < 2; L++) {
        const uint32_t inb  = (L == 0) ? BUFA : BUFB;
        const uint32_t outb = (L == 0) ? BUFB : BUFA;
        const uint32_t wbase = (uint32_t)L * NW * 8;

        // ---- expert B-slice + gate B + bias slice loads (issue early) ----
        const uint4* pg = gw4 + wbase + (uint32_t)(256 + qr) * 8 + qc * 2;
        uint4 Bg0 = pg[0], Bg1 = pg[1];
        uint4 Bx[4][2];
#pragma unroll
        for (int e = 0; e < 4; e++) {
            const uint4* p = gw4 + wbase + (uint32_t)(e * 64 + 8 * w + qr) * 8 + qc * 2;
            Bx[e][0] = p[0];
            Bx[e][1] = p[1];
        }
        float2 cf[4];
#pragma unroll
        for (int e = 0; e < 4; e++)
            cf[e] = ldsf2(CSM + ((uint32_t)L * 256 + e * 64 + 8 * w + 2 * qc) * 4);

        // ---- gate phase: warp w handles m-tile w ----
        {
            uint32_t Af[4][4];
            uint32_t ab = inb + (uint32_t)(w * 16) * (RS * 2) + lrow;
#pragma unroll
            for (int c = 0; c < 4; c++) ldsm_x4(Af[c], ab + c * 32);
            float acc[4] = {0.f, 0.f, 0.f, 0.f};
            mma16816(acc, Af[0], Bg0.x, Bg0.y);
            mma16816(acc, Af[1], Bg0.z, Bg0.w);
            mma16816(acc, Af[2], Bg1.x, Bg1.y);
            mma16816(acc, Af[3], Bg1.z, Bg1.w);
            const unsigned full = 0xffffffffu;
            const int qb = lane & ~3;
            float l0 = __shfl_sync(full, acc[0], qb);
            float l1 = __shfl_sync(full, acc[1], qb);
            float l2 = __shfl_sync(full, acc[0], qb + 1);
            float l3 = __shfl_sync(full, acc[1], qb + 1);
            float m0 = __shfl_sync(full, acc[2], qb);
            float m1 = __shfl_sync(full, acc[3], qb);
            float m2 = __shfl_sync(full, acc[2], qb + 1);
            float m3 = __shfl_sync(full, acc[3], qb + 1);
            float mxl = fmaxf(fmaxf(l0, l1), fmaxf(l2, l3));
            float e0 = __expf(l0 - mxl), e1 = __expf(l1 - mxl), e2 = __expf(l2 - mxl), e3 = __expf(l3 - mxl);
            float inv = 1.0f / (e0 + e1 + e2 + e3);
            float4 glo = make_float4(e0 * inv, e1 * inv, e2 * inv, e3 * inv);
            float mxh = fmaxf(fmaxf(m0, m1), fmaxf(m2, m3));
            float f0 = __expf(m0 - mxh), f1 = __expf(m1 - mxh), f2 = __expf(m2 - mxh), f3 = __expf(m3 - mxh);
            float inh = 1.0f / (f0 + f1 + f2 + f3);
            float4 ghi = make_float4(f0 * inh, f1 * inh, f2 * inh, f3 * inh);
            if (qc == 0) {
                stsf4(GSM + (uint32_t)(w * 16 + qr) * 16, glo);
                stsf4(GSM + (uint32_t)(w * 16 + qr + 8) * 16, ghi);
            }
        }
        __syncthreads();

        // ---- main: all 8 m-tiles, double-buffered A fragments ----
        uint32_t Af[2][4][4];
        {
            uint32_t ab = inb + lrow;
#pragma unroll
            for (int c = 0; c < 4; c++) ldsm_x4(Af[0][c], ab + c * 32);
        }
        float4 gl = ldsf4(GSM + (uint32_t)qr * 16);
        float4 gh = ldsf4(GSM + (uint32_t)(qr + 8) * 16);

#pragma unroll
        for (int mt = 0; mt < 8; mt++) {
            const int cur = mt & 1;
            float4 gln, ghn;
            if (mt < 7) {   // prefetch next tile's fragments + gates
                uint32_t ab = inb + (uint32_t)((mt + 1) * 16) * (RS * 2) + lrow;
#pragma unroll
                for (int c = 0; c < 4; c++) ldsm_x4(Af[cur ^ 1][c], ab + c * 32);
                gln = ldsf4(GSM + (uint32_t)((mt + 1) * 16 + qr) * 16);
                ghn = ldsf4(GSM + (uint32_t)((mt + 1) * 16 + qr + 8) * 16);
            }

            const float gle[4] = {gl.x, gl.y, gl.z, gl.w};
            const float ghe[4] = {gh.x, gh.y, gh.z, gh.w};
            float h0 = 0.f, h1 = 0.f, h2 = 0.f, h3 = 0.f;
#pragma unroll
            for (int e = 0; e < 4; e++) {
                float Y[4] = {0.f, 0.f, 0.f, 0.f};
                mma16816(Y, Af[cur][0], Bx[e][0].x, Bx[e][0].y);
                mma16816(Y, Af[cur][1], Bx[e][0].z, Bx[e][0].w);
                mma16816(Y, Af[cur][2], Bx[e][1].x, Bx[e][1].y);
                mma16816(Y, Af[cur][3], Bx[e][1].z, Bx[e][1].w);
                h0 = fmaf(gle[e], Y[0], h0);
                h1 = fmaf(gle[e], Y[1], h1);
                h2 = fmaf(ghe[e], Y[2], h2);
                h3 = fmaf(ghe[e], Y[3], h3);
            }
#pragma unroll
            for (int e = 0; e < 4; e++) {
                h0 = fmaf(-gle[e], cf[e].x, h0);
                h1 = fmaf(-gle[e], cf[e].y, h1);
                h2 = fmaf(-ghe[e], cf[e].x, h2);
                h3 = fmaf(-ghe[e], cf[e].y, h3);
            }
            uint32_t oc = (uint32_t)(8 * w + 2 * qc) * 2;
            sts32(outb + (uint32_t)(mt * 16 + qr) * (RS * 2) + oc, pack_bf16x2(h0, h1));
            sts32(outb + (uint32_t)(mt * 16 + qr + 8) * (RS * 2) + oc, pack_bf16x2(h2, h3));

            if (mt < 7) { gl = gln; gh = ghn; }
        }
        __syncthreads();
    }

    // ---- epilogue: h2 (BUFA) + residual x (fp32, L2-hot) -> out, coalesced ----
#pragma unroll
    for (int i = 0; i < 8; i++) {
        int idx = w * 1024 + i * 128 + lane * 4;
        int row = idx >> 6, col = idx & 63;
        long r = tok0 + row;
        if (r < Ntok) {
            uint2 hp = lds64(BUFA + (row * RS + col) * 2);
            float4 xr = *(const float4*)(x + r * 64 + col);
            float4 o = make_float4(bf_lo(hp.x) + xr.x, bf_hi(hp.x) + xr.y,
                                   bf_lo(hp.y) + xr.z, bf_hi(hp.y) + xr.w);
            *(float4*)(out + r * 64 + col) = o;
        }
    }
}

// ------------------------------ launch -------------------------------------
extern "C" void kernel_launch(void* const* d_in, const int* in_sizes, int n_in,
                              void* d_out, int out_size) {
    const float* x    = (const float*)d_in[0];
    const float* wg_a = (const float*)d_in[1];
    const float* we_a = (const float*)d_in[2];
    const float* be_a = (const float*)d_in[3];
    const float* wg_b = (const float*)d_in[4];
    const float* we_b = (const float*)d_in[5];
    const float* be_b = (const float*)d_in[6];
    const int Ntok = in_sizes[0] / DD;

    prep_kernel<<<2, 256>>>(wg_a, we_a, be_a, wg_b, we_b, be_b);

    const int smem_bytes = 2 * 128 * RS * 2 + 128 * 16 + 512 * 4;  // 41472
    cudaFuncSetAttribute(moe_main_kernel, cudaFuncAttributeMaxDynamicSharedMemorySize, smem_bytes);

    const int grid = (Ntok + 127) / 128;
    moe_main_kernel<<<grid, 256, smem_bytes>>>(x, (float*)d_out, Ntok);
}

// round 14
// speedup vs baseline: 1.1806x; 1.0826x over previous
#include <cuda_runtime.h>
#include <cuda_bf16.h>
#include <stdint.h>

// ---------------------------------------------------------------------------
// SPMoEAdaptor fused (2 soft-MoE layers + residual), sm_103a. R14 = R13 main
// kernel (n-split, 8 f-cols/warp in regs, double-buffered ldmatrix pipeline)
// + parallelized prep kernel (49x2 blocks, warp-reduced bias dot products).
// R13's prep ran on 2 blocks and cost ~13us of the 137.5us total.
// ---------------------------------------------------------------------------

#define DD 64
#define NW 264           // 256 expert cols + 4 gate cols + 4 zero pad
#define RS 72            // bf16 row stride in token buffers (144B, LDSM conflict-free)

__device__ __align__(16) uint2 g_wpack[2][NW][4][4];
__device__ float g_c[2][4][DD];   // c_e[f] = sum_d b[e,d]*W[e,d,f]

__device__ __forceinline__ uint32_t pack_bf16x2(float lo, float hi) {
    uint32_t r; asm("cvt.rn.bf16x2.f32 %0, %1, %2;" : "=r"(r) : "f"(hi), "f"(lo)); return r;
}
__device__ __forceinline__ float bf_lo(uint32_t u) { return __uint_as_float(u << 16); }
__device__ __forceinline__ float bf_hi(uint32_t u) { return __uint_as_float(u & 0xffff0000u); }

__device__ __forceinline__ uint32_t smem_u32(const void* p) {
    uint32_t a; asm("{ .reg .u64 t; cvta.to.shared.u64 t, %1; cvt.u32.u64 %0, t; }" : "=r"(a) : "l"(p)); return a;
}
__device__ __forceinline__ void sts32(uint32_t a, uint32_t v) {
    asm volatile("st.shared.b32 [%0], %1;" :: "r"(a), "r"(v) : "memory");
}
__device__ __forceinline__ void sts64(uint32_t a, uint32_t v0, uint32_t v1) {
    asm volatile("st.shared.v2.b32 [%0], {%1,%2};" :: "r"(a), "r"(v0), "r"(v1) : "memory");
}
__device__ __forceinline__ uint2 lds64(uint32_t a) {
    uint2 v; asm volatile("ld.shared.v2.b32 {%0,%1}, [%2];" : "=r"(v.x), "=r"(v.y) : "r"(a)); return v;
}
__device__ __forceinline__ float4 ldsf4(uint32_t a) {
    float4 v; asm volatile("ld.shared.v4.f32 {%0,%1,%2,%3}, [%4];"
        : "=f"(v.x), "=f"(v.y), "=f"(v.z), "=f"(v.w) : "r"(a)); return v;
}
__device__ __forceinline__ void stsf4(uint32_t a, float4 v) {
    asm volatile("st.shared.v4.f32 [%0], {%1,%2,%3,%4};" :: "r"(a), "f"(v.x), "f"(v.y), "f"(v.z), "f"(v.w) : "memory");
}
__device__ __forceinline__ float2 ldsf2(uint32_t a) {
    float2 v; asm volatile("ld.shared.v2.f32 {%0,%1}, [%2];" : "=f"(v.x), "=f"(v.y) : "r"(a)); return v;
}
__device__ __forceinline__ void ldsm_x4(uint32_t r[4], uint32_t a) {
    asm volatile("ldmatrix.sync.aligned.m8n8.x4.shared.b16 {%0,%1,%2,%3}, [%4];"
        : "=r"(r[0]), "=r"(r[1]), "=r"(r[2]), "=r"(r[3]) : "r"(a));
}
__device__ __forceinline__ void mma16816(float c[4], const uint32_t a[4], uint32_t b0, uint32_t b1) {
    asm volatile(
        "mma.sync.aligned.m16n8k16.row.col.f32.bf16.bf16.f32 "
        "{%0,%1,%2,%3}, {%4,%5,%6,%7}, {%8,%9}, {%0,%1,%2,%3};"
        : "+f"(c[0]), "+f"(c[1]), "+f"(c[2]), "+f"(c[3])
        : "r"(a[0]), "r"(a[1]), "r"(a[2]), "r"(a[3]), "r"(b0), "r"(b1));
}

// ------------------------------ prep kernel --------------------------------
// grid (49, 2): blocks 0..16 pack weights (one element/thread);
// blocks 17..48 compute g_c (one warp per (e,f), shfl-reduced).
__global__ void prep_kernel(const float* __restrict__ wg_a, const float* __restrict__ we_a,
                            const float* __restrict__ be_a,
                            const float* __restrict__ wg_b, const float* __restrict__ we_b,
                            const float* __restrict__ be_b) {
    const int L = blockIdx.y;
    const float* wg = L ? wg_b : wg_a;
    const float* we = L ? we_b : we_a;
    const float* be = L ? be_b : be_a;

    if (blockIdx.x < 17) {
        int idx = blockIdx.x * 256 + threadIdx.x;
        if (idx < NW * 16) {
            int n  = idx >> 4;
            int j  = (idx >> 2) & 3;
            int kk = idx & 3;
            float v[4];
#pragma unroll
            for (int h = 0; h < 4; h++) {
                int d = kk * 16 + 2 * j + (h >> 1) * 8 + (h & 1);
                float w;
                if (n < 256)        w = we[((n >> 6) * DD + d) * DD + (n & 63)]; // W_e[d][f]
                else if (n < 260)   w = wg[d * 4 + (n - 256)];                   // w_gate[d][e]
                else                w = 0.0f;
                v[h] = w;
            }
            uint2 u;
            u.x = pack_bf16x2(v[0], v[1]);
            u.y = pack_bf16x2(v[2], v[3]);
            g_wpack[L][n][j][kk] = u;
        }
    } else {
        // one warp per (e,f): c[e][f] = sum_d b[e,d] * W[e,d,f]
        int warp = (blockIdx.x - 17) * 8 + (threadIdx.x >> 5);   // 0..255
        int lane = threadIdx.x & 31;
        int e = warp >> 6, f = warp & 63;
        float s = be[e * DD + lane]      * we[(e * DD + lane) * DD + f]
                + be[e * DD + lane + 32] * we[(e * DD + lane + 32) * DD + f];
#pragma unroll
        for (int o = 16; o > 0; o >>= 1)
            s += __shfl_xor_sync(0xffffffffu, s, o);
        if (lane == 0) g_c[L][e][f] = s;
    }
}

// ------------------------------ main kernel --------------------------------
__global__ __launch_bounds__(256, 2)
void moe_main_kernel(const float* __restrict__ x, float* __restrict__ out, int Ntok) {
    extern __shared__ __align__(16) uint8_t smraw[];
    const uint32_t base = smem_u32(smraw);
    const uint32_t BUFA = base;                  // [128][RS] bf16 (x / h2)
    const uint32_t BUFB = base + 128 * RS * 2;   // [128][RS] bf16 (h1)
    const uint32_t GSM  = BUFB + 128 * RS * 2;   // [128][4] f32 gates
    const uint32_t CSM  = GSM + 128 * 16;        // [2][4][64] f32 bias

    const int tid  = threadIdx.x;
    const int w    = tid >> 5;
    const int lane = tid & 31;
    const int qr   = lane >> 2;
    const int qc   = lane & 3;
    const long tok0 = (long)blockIdx.x * 128;

    for (int i = tid; i < 512; i += 256)
        sts32(CSM + i * 4, ((const uint32_t*)g_c)[i]);

    // ---- stage x -> BUFA (bf16), fully coalesced ----
#pragma unroll
    for (int i = 0; i < 8; i++) {
        int idx = w * 1024 + i * 128 + lane * 4;     // 0..8191 floats
        int row = idx >> 6, col = idx & 63;
        long r = tok0 + row;
        float4 v = (r < Ntok) ? *(const float4*)(x + r * 64 + col)
                              : make_float4(0.f, 0.f, 0.f, 0.f);
        sts64(BUFA + (row * RS + col) * 2, pack_bf16x2(v.x, v.y), pack_bf16x2(v.z, v.w));
    }
    __syncthreads();

    const uint32_t lrow = (uint32_t)(lane & 15) * (RS * 2) + (uint32_t)(lane >> 4) * 16;
    const uint4* gw4 = (const uint4*)g_wpack;    // 8 uint4 per n-row

#pragma unroll
    for (int L = 0; L < 2; L++) {
        const uint32_t inb  = (L == 0) ? BUFA : BUFB;
        const uint32_t outb = (L == 0) ? BUFB : BUFA;
        const uint32_t wbase = (uint32_t)L * NW * 8;

        // ---- expert B-slice + gate B + bias slice loads (issue early) ----
        const uint4* pg = gw4 + wbase + (uint32_t)(256 + qr) * 8 + qc * 2;
        uint4 Bg0 = pg[0], Bg1 = pg[1];
        uint4 Bx[4][2];
#pragma unroll
        for (int e = 0; e < 4; e++) {
            const uint4* p = gw4 + wbase + (uint32_t)(e * 64 + 8 * w + qr) * 8 + qc * 2;
            Bx[e][0] = p[0];
            Bx[e][1] = p[1];
        }
        float2 cf[4];
#pragma unroll
        for (int e = 0; e < 4; e++)
            cf[e] = ldsf2(CSM + ((uint32_t)L * 256 + e * 64 + 8 * w + 2 * qc) * 4);

        // ---- gate phase: warp w handles m-tile w ----
        {
            uint32_t Af[4][4];
            uint32_t ab = inb + (uint32_t)(w * 16) * (RS * 2) + lrow;
#pragma unroll
            for (int c = 0; c < 4; c++) ldsm_x4(Af[c], ab + c * 32);
            float acc[4] = {0.f, 0.f, 0.f, 0.f};
            mma16816(acc, Af[0], Bg0.x, Bg0.y);
            mma16816(acc, Af[1], Bg0.z, Bg0.w);
            mma16816(acc, Af[2], Bg1.x, Bg1.y);
            mma16816(acc, Af[3], Bg1.z, Bg1.w);
            const unsigned full = 0xffffffffu;
            const int qb = lane & ~3;
            float l0 = __shfl_sync(full, acc[0], qb);
            float l1 = __shfl_sync(full, acc[1], qb);
            float l2 = __shfl_sync(full, acc[0], qb + 1);
            float l3 = __shfl_sync(full, acc[1], qb + 1);
            float m0 = __shfl_sync(full, acc[2], qb);
            float m1 = __shfl_sync(full, acc[3], qb);
            float m2 = __shfl_sync(full, acc[2], qb + 1);
            float m3 = __shfl_sync(full, acc[3], qb + 1);
            float mxl = fmaxf(fmaxf(l0, l1), fmaxf(l2, l3));
            float e0 = __expf(l0 - mxl), e1 = __expf(l1 - mxl), e2 = __expf(l2 - mxl), e3 = __expf(l3 - mxl);
            float inv = 1.0f / (e0 + e1 + e2 + e3);
            float4 glo = make_float4(e0 * inv, e1 * inv, e2 * inv, e3 * inv);
            float mxh = fmaxf(fmaxf(m0, m1), fmaxf(m2, m3));
            float f0 = __expf(m0 - mxh), f1 = __expf(m1 - mxh), f2 = __expf(m2 - mxh), f3 = __expf(m3 - mxh);
            float inh = 1.0f / (f0 + f1 + f2 + f3);
            float4 ghi = make_float4(f0 * inh, f1 * inh, f2 * inh, f3 * inh);
            if (qc == 0) {
                stsf4(GSM + (uint32_t)(w * 16 + qr) * 16, glo);
                stsf4(GSM + (uint32_t)(w * 16 + qr + 8) * 16, ghi);
            }
        }
        __syncthreads();

        // ---- main: all 8 m-tiles, double-buffered A fragments ----
        uint32_t Af[2][4][4];
        {
            uint32_t ab = inb + lrow;
#pragma unroll
            for (int c = 0; c < 4; c++) ldsm_x4(Af[0][c], ab + c * 32);
        }
        float4 gl = ldsf4(GSM + (uint32_t)qr * 16);
        float4 gh = ldsf4(GSM + (uint32_t)(qr + 8) * 16);

#pragma unroll
        for (int mt = 0; mt < 8; mt++) {
            const int cur = mt & 1;
            float4 gln, ghn;
            if (mt < 7) {   // prefetch next tile's fragments + gates
                uint32_t ab = inb + (uint32_t)((mt + 1) * 16) * (RS * 2) + lrow;
#pragma unroll
                for (int c = 0; c < 4; c++) ldsm_x4(Af[cur ^ 1][c], ab + c * 32);
                gln = ldsf4(GSM + (uint32_t)((mt + 1) * 16 + qr) * 16);
                ghn = ldsf4(GSM + (uint32_t)((mt + 1) * 16 + qr + 8) * 16);
            }

            const float gle[4] = {gl.x, gl.y, gl.z, gl.w};
            const float ghe[4] = {gh.x, gh.y, gh.z, gh.w};
            float h0 = 0.f, h1 = 0.f, h2 = 0.f, h3 = 0.f;
#pragma unroll
            for (int e = 0; e < 4; e++) {
                float Y[4] = {0.f, 0.f, 0.f, 0.f};
                mma16816(Y, Af[cur][0], Bx[e][0].x, Bx[e][0].y);
                mma16816(Y, Af[cur][1], Bx[e][0].z, Bx[e][0].w);
                mma16816(Y, Af[cur][2], Bx[e][1].x, Bx[e][1].y);
                mma16816(Y, Af[cur][3], Bx[e][1].z, Bx[e][1].w);
                h0 = fmaf(gle[e], Y[0], h0);
                h1 = fmaf(gle[e], Y[1], h1);
                h2 = fmaf(ghe[e], Y[2], h2);
                h3 = fmaf(ghe[e], Y[3], h3);
            }
#pragma unroll
            for (int e = 0; e < 4; e++) {
                h0 = fmaf(-gle[e], cf[e].x, h0);
                h1 = fmaf(-gle[e], cf[e].y, h1);
                h2 = fmaf(-ghe[e], cf[e].x, h2);
                h3 = fmaf(-ghe[e], cf[e].y, h3);
            }
            uint32_t oc = (uint32_t)(8 * w + 2 * qc) * 2;
            sts32(outb + (uint32_t)(mt * 16 + qr) * (RS * 2) + oc, pack_bf16x2(h0, h1));
            sts32(outb + (uint32_t)(mt * 16 + qr + 8) * (RS * 2) + oc, pack_bf16x2(h2, h3));

            if (mt < 7) { gl = gln; gh = ghn; }
        }
        __syncthreads();
    }

    // ---- epilogue: h2 (BUFA) + residual x (fp32, L2-hot) -> out, coalesced ----
#pragma unroll
    for (int i = 0; i < 8; i++) {
        int idx = w * 1024 + i * 128 + lane * 4;
        int row = idx >> 6, col = idx & 63;
        long r = tok0 + row;
        if (r < Ntok) {
            uint2 hp = lds64(BUFA + (row * RS + col) * 2);
            float4 xr = *(const float4*)(x + r * 64 + col);
            float4 o = make_float4(bf_lo(hp.x) + xr.x, bf_hi(hp.x) + xr.y,
                                   bf_lo(hp.y) + xr.z, bf_hi(hp.y) + xr.w);
            *(float4*)(out + r * 64 + col) = o;
        }
    }
}

// ------------------------------ launch -------------------------------------
extern "C" void kernel_launch(void* const* d_in, const int* in_sizes, int n_in,
                              void* d_out, int out_size) {
    const float* x    = (const float*)d_in[0];
    const float* wg_a = (const float*)d_in[1];
    const float* we_a = (const float*)d_in[2];
    const float* be_a = (const float*)d_in[3];
    const float* wg_b = (const float*)d_in[4];
    const float* we_b = (const float*)d_in[5];
    const float* be_b = (const float*)d_in[6];
    const int Ntok = in_sizes[0] / DD;

    prep_kernel<<<dim3(49, 2), 256>>>(wg_a, we_a, be_a, wg_b, we_b, be_b);

    const int smem_bytes = 2 * 128 * RS * 2 + 128 * 16 + 512 * 4;  // 41472
    cudaFuncSetAttribute(moe_main_kernel, cudaFuncAttributeMaxDynamicSharedMemorySize, smem_bytes);

    const int grid = (Ntok + 127) / 128;
    moe_main_kernel<<<grid, 256, smem_bytes>>>(x, (float*)d_out, Ntok);
}